// round 6
// baseline (speedup 1.0000x reference)
#include <cuda_runtime.h>
#include <cuda_bf16.h>
#include <cstdint>

#define BT 8
#define SEQ 4096
#define NST 256
#define DIN 256
#define DOUT 256
#define M_TOT (BT*SEQ)          // 32768
#define CHUNK 64
#define NCHUNK (SEQ/CHUNK)      // 64

typedef unsigned long long u64;
typedef __nv_bfloat16 bf16;

// ---------------- device scratch ----------------
__device__ float g_Ar[NST], g_Ai[NST];
__device__ float g_ALr[NST], g_ALi[NST];
__device__ bf16  g_xh[(size_t)M_TOT*DIN], g_xl[(size_t)M_TOT*DIN];
__device__ bf16  g_W1h[512*DIN], g_W1l[512*DIN];   // [Bbar_r; Bbar_i]
__device__ bf16  g_W2h[DOUT*512], g_W2l[DOUT*512]; // [Cr | -Ci]
__device__ float g_u[(size_t)M_TOT*512];      // u: [:,0:256]=real  [:,256:512]=imag
__device__ bf16  g_hh[(size_t)M_TOT*512];     // h hi: [hr | hi_part]
__device__ bf16  g_hl[(size_t)M_TOT*512];     // h lo
__device__ float g_cr[BT*NCHUNK*NST], g_ci[BT*NCHUNK*NST];
__device__ float g_pr[BT*NCHUNK*NST], g_pi[BT*NCHUNK*NST];

__device__ __forceinline__ void bsplit(float v, bf16& h, bf16& l) {
    h = __float2bfloat16(v);
    l = __float2bfloat16(v - __bfloat162float(h));
}

// mma.sync m16n8k16 row.col bf16 -> f32 accumulate
__device__ __forceinline__ void hmma(float* d, const uint32_t* a, const uint32_t* b) {
    asm volatile(
        "mma.sync.aligned.m16n8k16.row.col.f32.bf16.bf16.f32 "
        "{%0,%1,%2,%3}, {%4,%5,%6,%7}, {%8,%9}, {%0,%1,%2,%3};"
        : "+f"(d[0]), "+f"(d[1]), "+f"(d[2]), "+f"(d[3])
        : "r"(a[0]), "r"(a[1]), "r"(a[2]), "r"(a[3]), "r"(b[0]), "r"(b[1]));
}
__device__ __forceinline__ void ldsm_x4(uint32_t* r, uint32_t addr) {
    asm volatile("ldmatrix.sync.aligned.m8n8.x4.shared.b16 {%0,%1,%2,%3}, [%4];"
        : "=r"(r[0]), "=r"(r[1]), "=r"(r[2]), "=r"(r[3]) : "r"(addr));
}
__device__ __forceinline__ void cpa16(uint32_t saddr, const void* g) {
    asm volatile("cp.async.cg.shared.global [%0], [%1], 16;" :: "r"(saddr), "l"(g));
}
__device__ __forceinline__ uint32_t smem_u32(const void* p) {
    uint32_t a;
    asm("{ .reg .u64 t; cvta.to.shared.u64 t, %1; cvt.u32.u64 %0, t; }" : "=r"(a) : "l"(p));
    return a;
}

// ---------------- setup ----------------
__global__ void k_setup(const float* __restrict__ llr, const float* __restrict__ lim,
                        const float* __restrict__ ldt, const float* __restrict__ Bm) {
    int n = threadIdx.x;
    float lr = -expf(llr[n]);
    float li = lim[n];
    float dt = expf(ldt[n]);
    dt = fminf(fmaxf(dt, 0.005f), 0.1f);
    float dr = 1.f - 0.5f * dt * lr;
    float di = -0.5f * dt * li;
    float nr = 1.f + 0.5f * dt * lr;
    float ni = 0.5f * dt * li;
    float inv = 1.f / (dr*dr + di*di);
    float Ar = (nr*dr + ni*di) * inv;
    float Ai = (ni*dr - nr*di) * inv;
    g_Ar[n] = Ar; g_Ai[n] = Ai;
    float wr = dt * dr * inv;
    float wi = -dt * di * inv;
    for (int k = 0; k < DIN; k++) {
        float b = Bm[n*DIN + k];
        bsplit(wr*b, g_W1h[n*DIN + k], g_W1l[n*DIN + k]);
        bsplit(wi*b, g_W1h[(256+n)*DIN + k], g_W1l[(256+n)*DIN + k]);
    }
    float pr = 1.f, pi = 0.f;
    for (int j = 0; j < CHUNK; j++) {
        float t = pr*Ar - pi*Ai;
        pi = pr*Ai + pi*Ar;
        pr = t;
    }
    g_ALr[n] = pr; g_ALi[n] = pi;
}

__global__ void k_w2(const float* __restrict__ Cr, const float* __restrict__ Ci) {
    int idx = blockIdx.x * blockDim.x + threadIdx.x;   // over 256*512
    int d = idx >> 9, k = idx & 511;
    float v = (k < 256) ? Cr[d*256 + k] : -Ci[d*256 + (k - 256)];
    bsplit(v, g_W2h[idx], g_W2l[idx]);
}

// convert x -> bf16 hi/lo
__global__ __launch_bounds__(256) void k_cvt(const float* __restrict__ x) {
    size_t i = (size_t)(blockIdx.x * blockDim.x + threadIdx.x) * 4;
    float4 v = *(const float4*)&x[i];
    bf16 h0,l0,h1,l1,h2,l2,h3,l3;
    bsplit(v.x,h0,l0); bsplit(v.y,h1,l1); bsplit(v.z,h2,l2); bsplit(v.w,h3,l3);
    __nv_bfloat162 hh0={h0,h1}, hh1={h2,h3}, ll0={l0,l1}, ll1={l2,l3};
    *(uint2*)&g_xh[i] = make_uint2(*(uint32_t*)&hh0, *(uint32_t*)&hh1);
    *(uint2*)&g_xl[i] = make_uint2(*(uint32_t*)&ll0, *(uint32_t*)&ll1);
}

// ---------------- HMMA GEMM (cp.async double-buffered, ldmatrix) ----------------
// C[M,Ntot] = A @ W^T. A bf16 hi/lo [M,lda]; W bf16 hi/lo [Ntot,Kdim]; out fp32 (ldc).
// Block tile 128x128, Kchunk 64, 2 stages. 8 warps: wm=wid>>1 (32 rows), wn=wid&1 (64 cols).
#define SROW 72
#define TILE (128*SROW)                 // bf16 elements per tile
#define STAGE (4*TILE)                  // Ah,Al,Wh,Wl
#define SMEM_SZ (2*STAGE*2)             // bytes

__global__ __launch_bounds__(256, 1) void k_gemm(
    const bf16* __restrict__ Ah, const bf16* __restrict__ Al, int lda,
    const bf16* __restrict__ Wh, const bf16* __restrict__ Wl,
    float* __restrict__ out, int ldc, int Kdim)
{
    extern __shared__ bf16 smem[];
    const uint32_t sb = smem_u32(smem);
    const int tid = threadIdx.x;
    const int wid = tid >> 5, lane = tid & 31;
    const int m0 = blockIdx.y * 128;
    const int n0 = blockIdx.x * 128;
    const int wm = wid >> 1;
    const int wn = wid & 1;
    const int g  = lane >> 2;
    const int q4 = lane & 3;

    float acc[2][8][4];
    #pragma unroll
    for (int i = 0; i < 2; i++)
        #pragma unroll
        for (int j = 0; j < 8; j++)
            #pragma unroll
            for (int r = 0; r < 4; r++) acc[i][j][r] = 0.f;

    const int nchunks = Kdim / 64;

    // ldmatrix lane addressing
    const int a_row = (lane & 7) + ((lane >> 3) & 1) * 8;   // 0..15
    const int a_ch  = (lane >> 4) * 8;                      // 0 or 8
    const int w_row = (lane & 7) + ((lane >> 4) & 1) * 8;
    const int w_ch  = ((lane >> 3) & 1) * 8;

    auto prefetch = [&](int stage, int ch) {
        const int k0 = ch * 64;
        const uint32_t s0 = sb + (uint32_t)stage * STAGE * 2;
        #pragma unroll
        for (int i = 0; i < 4; i++) {
            int v = tid + i * 256;
            int row = v >> 3, q = v & 7;
            uint32_t so = (uint32_t)(row * SROW + q * 8) * 2;
            const size_t ga = (size_t)(m0 + row) * lda + k0 + q * 8;
            const size_t gw = (size_t)(n0 + row) * Kdim + k0 + q * 8;
            cpa16(s0 + so,               Ah + ga);
            cpa16(s0 + TILE*2 + so,      Al + ga);
            cpa16(s0 + 2*TILE*2 + so,    Wh + gw);
            cpa16(s0 + 3*TILE*2 + so,    Wl + gw);
        }
        asm volatile("cp.async.commit_group;");
    };

    prefetch(0, 0);

    for (int ch = 0; ch < nchunks; ch++) {
        const int st = ch & 1;
        if (ch + 1 < nchunks) {
            prefetch(st ^ 1, ch + 1);
            asm volatile("cp.async.wait_group 1;");
        } else {
            asm volatile("cp.async.wait_group 0;");
        }
        __syncthreads();

        const uint32_t s0 = sb + (uint32_t)st * STAGE * 2;
        const uint32_t sAh = s0;
        const uint32_t sAl = s0 + TILE*2;
        const uint32_t sWh = s0 + 2*TILE*2;
        const uint32_t sWl = s0 + 3*TILE*2;

        #pragma unroll
        for (int ks = 0; ks < 4; ks++) {
            const int kk = ks * 16;
            // W fragments: 4 pairs x (hi,lo)
            uint32_t bh[8][2], bl[8][2];
            #pragma unroll
            for (int p = 0; p < 4; p++) {
                int nrow = wn*64 + p*16 + w_row;
                uint32_t off = (uint32_t)(nrow * SROW + kk + w_ch) * 2;
                uint32_t t[4];
                ldsm_x4(t, sWh + off);
                bh[2*p][0]=t[0]; bh[2*p][1]=t[1]; bh[2*p+1][0]=t[2]; bh[2*p+1][1]=t[3];
                ldsm_x4(t, sWl + off);
                bl[2*p][0]=t[0]; bl[2*p][1]=t[1]; bl[2*p+1][0]=t[2]; bl[2*p+1][1]=t[3];
            }
            // A fragments
            uint32_t ah[2][4], al[2][4];
            #pragma unroll
            for (int mf = 0; mf < 2; mf++) {
                int row = wm*32 + mf*16 + a_row;
                uint32_t off = (uint32_t)(row * SROW + kk + a_ch) * 2;
                ldsm_x4(ah[mf], sAh + off);
                ldsm_x4(al[mf], sAl + off);
            }
            #pragma unroll
            for (int nf = 0; nf < 8; nf++) {
                #pragma unroll
                for (int mf = 0; mf < 2; mf++) {
                    hmma(acc[mf][nf], ah[mf], bh[nf]);
                    hmma(acc[mf][nf], ah[mf], bl[nf]);
                    hmma(acc[mf][nf], al[mf], bh[nf]);
                }
            }
        }
        __syncthreads();
    }

    // ---- epilogue ----
    #pragma unroll
    for (int mf = 0; mf < 2; mf++) {
        int row = m0 + wm*32 + mf*16 + g;
        #pragma unroll
        for (int nf = 0; nf < 8; nf++) {
            int col = n0 + wn*64 + nf*8 + q4*2;
            *(float2*)&out[(size_t)row * ldc + col]       = make_float2(acc[mf][nf][0], acc[mf][nf][1]);
            *(float2*)&out[(size_t)(row + 8) * ldc + col] = make_float2(acc[mf][nf][2], acc[mf][nf][3]);
        }
    }
}

// ---------------- scan pass 1: chunk end states only ----------------
__global__ __launch_bounds__(256) void k_scan1() {
    const int b = blockIdx.x / NCHUNK, c = blockIdx.x % NCHUNK;
    const int n = threadIdx.x;
    const float Ar = g_Ar[n], Ai = g_Ai[n];
    size_t base = ((size_t)b*SEQ + (size_t)c*CHUNK) * 512 + n;
    float hr = 0.f, hi = 0.f;
    #pragma unroll 8
    for (int j = 0; j < CHUNK; j++) {
        float ur = g_u[base], ui = g_u[base + 256];
        float nhr = fmaf(Ar, hr, fmaf(-Ai, hi, ur));
        float nhi = fmaf(Ar, hi, fmaf( Ai, hr, ui));
        hr = nhr; hi = nhi;
        base += 512;
    }
    g_cr[(b*NCHUNK + c)*NST + n] = hr;
    g_ci[(b*NCHUNK + c)*NST + n] = hi;
}

// ---------------- scan pass 2: cross-chunk prefix, batched loads ----------------
__global__ __launch_bounds__(256) void k_scan2() {
    const int b = blockIdx.x;
    const int n = threadIdx.x;
    const float Ar = g_ALr[n], Ai = g_ALi[n];
    float hr = 0.f, hi = 0.f;
    for (int cb = 0; cb < 4; cb++) {
        float cr[16], ci[16];
        #pragma unroll
        for (int i = 0; i < 16; i++) {
            int idx = (b*NCHUNK + cb*16 + i)*NST + n;
            cr[i] = g_cr[idx]; ci[i] = g_ci[idx];
        }
        #pragma unroll
        for (int i = 0; i < 16; i++) {
            int idx = (b*NCHUNK + cb*16 + i)*NST + n;
            g_pr[idx] = hr; g_pi[idx] = hi;
            float nhr = fmaf(Ar, hr, fmaf(-Ai, hi, cr[i]));
            float nhi = fmaf(Ar, hi, fmaf( Ai, hr, ci[i]));
            hr = nhr; hi = nhi;
        }
    }
}

// ---------------- scan pass 3: full scan with carry, emit h as bf16 hi/lo ----------------
__global__ __launch_bounds__(256) void k_scan3() {
    const int b = blockIdx.x / NCHUNK, c = blockIdx.x % NCHUNK;
    const int n = threadIdx.x;
    const float Ar = g_Ar[n], Ai = g_Ai[n];
    float hr = g_pr[(b*NCHUNK + c)*NST + n];
    float hi = g_pi[(b*NCHUNK + c)*NST + n];
    size_t base = ((size_t)b*SEQ + (size_t)c*CHUNK) * 512 + n;
    #pragma unroll 8
    for (int j = 0; j < CHUNK; j++) {
        float ur = g_u[base], ui = g_u[base + 256];
        float nhr = fmaf(Ar, hr, fmaf(-Ai, hi, ur));
        float nhi = fmaf(Ar, hi, fmaf( Ai, hr, ui));
        hr = nhr; hi = nhi;
        bsplit(hr, g_hh[base],       g_hl[base]);
        bsplit(hi, g_hh[base + 256], g_hl[base + 256]);
        base += 512;
    }
}

// ---------------- launch ----------------
extern "C" void kernel_launch(void* const* d_in, const int* in_sizes, int n_in,
                              void* d_out, int out_size) {
    const float* x   = (const float*)d_in[0];
    const float* llr = (const float*)d_in[1];
    const float* lim = (const float*)d_in[2];
    const float* ldt = (const float*)d_in[3];
    const float* Bm  = (const float*)d_in[4];
    const float* Cr  = (const float*)d_in[5];
    const float* Ci  = (const float*)d_in[6];
    float* out = (float*)d_out;

    cudaFuncSetAttribute(k_gemm, cudaFuncAttributeMaxDynamicSharedMemorySize, SMEM_SZ);

    bf16 *xh, *xl, *w1h, *w1l, *w2h, *w2l, *hh, *hl;
    float *u;
    cudaGetSymbolAddress((void**)&xh, g_xh);
    cudaGetSymbolAddress((void**)&xl, g_xl);
    cudaGetSymbolAddress((void**)&w1h, g_W1h);
    cudaGetSymbolAddress((void**)&w1l, g_W1l);
    cudaGetSymbolAddress((void**)&w2h, g_W2h);
    cudaGetSymbolAddress((void**)&w2l, g_W2l);
    cudaGetSymbolAddress((void**)&hh, g_hh);
    cudaGetSymbolAddress((void**)&hl, g_hl);
    cudaGetSymbolAddress((void**)&u, g_u);

    k_setup<<<1, 256>>>(llr, lim, ldt, Bm);
    k_w2<<<(256*512)/256, 256>>>(Cr, Ci);
    k_cvt<<<(M_TOT*DIN/4)/256, 256>>>(x);
    // GEMM1: u[M,512] = x @ [Bbar_r;Bbar_i]^T
    k_gemm<<<dim3(512/128, M_TOT/128), 256, SMEM_SZ>>>(xh, xl, DIN, w1h, w1l, u, 512, DIN);
    k_scan1<<<BT*NCHUNK, 256>>>();
    k_scan2<<<BT, 256>>>();
    k_scan3<<<BT*NCHUNK, 256>>>();
    // GEMM2: out[M,256] = [hr|hi] @ [Cr|-Ci]^T   (Kdim = 512!)
    k_gemm<<<dim3(DOUT/128, M_TOT/128), 256, SMEM_SZ>>>(hh, hl, 512, w2h, w2l, out, DOUT, 512);
}

// round 7
// speedup vs baseline: 2.2440x; 2.2440x over previous
#include <cuda_runtime.h>
#include <cuda_bf16.h>
#include <cstdint>

#define BT 8
#define SEQ 4096
#define NST 256
#define DIN 256
#define DOUT 256
#define M_TOT (BT*SEQ)          // 32768
#define CHUNK 64
#define NCHUNK (SEQ/CHUNK)      // 64

typedef unsigned long long u64;
typedef __nv_bfloat16 bf16;

// ---------------- device scratch ----------------
__device__ float g_Ar[NST], g_Ai[NST];
__device__ float g_ALr[NST], g_ALi[NST];
__device__ float g_wr[NST], g_wi[NST];
__device__ bf16  g_xh[(size_t)M_TOT*DIN], g_xl[(size_t)M_TOT*DIN];
__device__ bf16  g_W1h[512*DIN], g_W1l[512*DIN];   // [Bbar_r; Bbar_i]
__device__ bf16  g_W2h[DOUT*512], g_W2l[DOUT*512]; // [Cr | -Ci]
__device__ float g_u[(size_t)M_TOT*512];      // u: [:,0:256]=real  [:,256:512]=imag
__device__ bf16  g_hh[(size_t)M_TOT*512];     // h hi: [hr | hi_part]
__device__ bf16  g_hl[(size_t)M_TOT*512];     // h lo
__device__ float g_cr[BT*NCHUNK*NST], g_ci[BT*NCHUNK*NST];
__device__ float g_pr[BT*NCHUNK*NST], g_pi[BT*NCHUNK*NST];

__device__ __forceinline__ void bsplit(float v, bf16& h, bf16& l) {
    h = __float2bfloat16(v);
    l = __float2bfloat16(v - __bfloat162float(h));
}

// mma.sync m16n8k16 row.col bf16 -> f32 accumulate
__device__ __forceinline__ void hmma(float* d, const uint32_t* a, const uint32_t* b) {
    asm volatile(
        "mma.sync.aligned.m16n8k16.row.col.f32.bf16.bf16.f32 "
        "{%0,%1,%2,%3}, {%4,%5,%6,%7}, {%8,%9}, {%0,%1,%2,%3};"
        : "+f"(d[0]), "+f"(d[1]), "+f"(d[2]), "+f"(d[3])
        : "r"(a[0]), "r"(a[1]), "r"(a[2]), "r"(a[3]), "r"(b[0]), "r"(b[1]));
}
__device__ __forceinline__ void ldsm_x4(uint32_t* r, uint32_t addr) {
    asm volatile("ldmatrix.sync.aligned.m8n8.x4.shared.b16 {%0,%1,%2,%3}, [%4];"
        : "=r"(r[0]), "=r"(r[1]), "=r"(r[2]), "=r"(r[3]) : "r"(addr));
}
__device__ __forceinline__ void cpa16(uint32_t saddr, const void* g) {
    asm volatile("cp.async.cg.shared.global [%0], [%1], 16;" :: "r"(saddr), "l"(g));
}
__device__ __forceinline__ uint32_t smem_u32(const void* p) {
    uint32_t a;
    asm("{ .reg .u64 t; cvta.to.shared.u64 t, %1; cvt.u32.u64 %0, t; }" : "=r"(a) : "l"(p));
    return a;
}

// ---------------- setup: per-n scalars only (fast) ----------------
__global__ void k_setup(const float* __restrict__ llr, const float* __restrict__ lim,
                        const float* __restrict__ ldt) {
    int n = threadIdx.x;
    float lr = -expf(llr[n]);
    float li = lim[n];
    float dt = expf(ldt[n]);
    dt = fminf(fmaxf(dt, 0.005f), 0.1f);
    float dr = 1.f - 0.5f * dt * lr;
    float di = -0.5f * dt * li;
    float nr = 1.f + 0.5f * dt * lr;
    float ni = 0.5f * dt * li;
    float inv = 1.f / (dr*dr + di*di);
    float Ar = (nr*dr + ni*di) * inv;
    float Ai = (ni*dr - nr*di) * inv;
    g_Ar[n] = Ar; g_Ai[n] = Ai;
    g_wr[n] = dt * dr * inv;
    g_wi[n] = -dt * di * inv;
    float pr = 1.f, pi = 0.f;
    for (int j = 0; j < CHUNK; j++) {
        float t = pr*Ar - pi*Ai;
        pi = pr*Ai + pi*Ar;
        pr = t;
    }
    g_ALr[n] = pr; g_ALi[n] = pi;
}

// W1 rows: [0:256) = wr[n]*B[n,:],  [256:512) = wi[n]*B[n,:]  (coalesced)
__global__ __launch_bounds__(256) void k_w1(const float* __restrict__ Bm) {
    int idx = blockIdx.x * blockDim.x + threadIdx.x;   // over 256*256
    int n = idx >> 8, k = idx & 255;
    float b = Bm[idx];
    bsplit(g_wr[n] * b, g_W1h[idx],             g_W1l[idx]);
    bsplit(g_wi[n] * b, g_W1h[(256+n)*DIN + k], g_W1l[(256+n)*DIN + k]);
}

__global__ void k_w2(const float* __restrict__ Cr, const float* __restrict__ Ci) {
    int idx = blockIdx.x * blockDim.x + threadIdx.x;   // over 256*512
    int d = idx >> 9, k = idx & 511;
    float v = (k < 256) ? Cr[d*256 + k] : -Ci[d*256 + (k - 256)];
    bsplit(v, g_W2h[idx], g_W2l[idx]);
}

// convert x -> bf16 hi/lo
__global__ __launch_bounds__(256) void k_cvt(const float* __restrict__ x) {
    size_t i = (size_t)(blockIdx.x * blockDim.x + threadIdx.x) * 4;
    float4 v = *(const float4*)&x[i];
    bf16 h0,l0,h1,l1,h2,l2,h3,l3;
    bsplit(v.x,h0,l0); bsplit(v.y,h1,l1); bsplit(v.z,h2,l2); bsplit(v.w,h3,l3);
    __nv_bfloat162 hh0={h0,h1}, hh1={h2,h3}, ll0={l0,l1}, ll1={l2,l3};
    *(uint2*)&g_xh[i] = make_uint2(*(uint32_t*)&hh0, *(uint32_t*)&hh1);
    *(uint2*)&g_xl[i] = make_uint2(*(uint32_t*)&ll0, *(uint32_t*)&ll1);
}

// ---------------- HMMA GEMM (cp.async double-buffered, ldmatrix) ----------------
#define SROW 72
#define TILE (128*SROW)                 // bf16 elements per tile
#define STAGE (4*TILE)                  // Ah,Al,Wh,Wl
#define SMEM_SZ (2*STAGE*2)             // bytes

__global__ __launch_bounds__(256, 1) void k_gemm(
    const bf16* __restrict__ Ah, const bf16* __restrict__ Al, int lda,
    const bf16* __restrict__ Wh, const bf16* __restrict__ Wl,
    float* __restrict__ out, int ldc, int Kdim)
{
    extern __shared__ bf16 smem[];
    const uint32_t sb = smem_u32(smem);
    const int tid = threadIdx.x;
    const int wid = tid >> 5, lane = tid & 31;
    const int m0 = blockIdx.y * 128;
    const int n0 = blockIdx.x * 128;
    const int wm = wid >> 1;
    const int wn = wid & 1;
    const int g  = lane >> 2;
    const int q4 = lane & 3;

    float acc[2][8][4];
    #pragma unroll
    for (int i = 0; i < 2; i++)
        #pragma unroll
        for (int j = 0; j < 8; j++)
            #pragma unroll
            for (int r = 0; r < 4; r++) acc[i][j][r] = 0.f;

    const int nchunks = Kdim / 64;

    const int a_row = (lane & 7) + ((lane >> 3) & 1) * 8;
    const int a_ch  = (lane >> 4) * 8;
    const int w_row = (lane & 7) + ((lane >> 4) & 1) * 8;
    const int w_ch  = ((lane >> 3) & 1) * 8;

    auto prefetch = [&](int stage, int ch) {
        const int k0 = ch * 64;
        const uint32_t s0 = sb + (uint32_t)stage * STAGE * 2;
        #pragma unroll
        for (int i = 0; i < 4; i++) {
            int v = tid + i * 256;
            int row = v >> 3, q = v & 7;
            uint32_t so = (uint32_t)(row * SROW + q * 8) * 2;
            const size_t ga = (size_t)(m0 + row) * lda + k0 + q * 8;
            const size_t gw = (size_t)(n0 + row) * Kdim + k0 + q * 8;
            cpa16(s0 + so,               Ah + ga);
            cpa16(s0 + TILE*2 + so,      Al + ga);
            cpa16(s0 + 2*TILE*2 + so,    Wh + gw);
            cpa16(s0 + 3*TILE*2 + so,    Wl + gw);
        }
        asm volatile("cp.async.commit_group;");
    };

    prefetch(0, 0);

    for (int ch = 0; ch < nchunks; ch++) {
        const int st = ch & 1;
        if (ch + 1 < nchunks) {
            prefetch(st ^ 1, ch + 1);
            asm volatile("cp.async.wait_group 1;");
        } else {
            asm volatile("cp.async.wait_group 0;");
        }
        __syncthreads();

        const uint32_t s0 = sb + (uint32_t)st * STAGE * 2;
        const uint32_t sAh = s0;
        const uint32_t sAl = s0 + TILE*2;
        const uint32_t sWh = s0 + 2*TILE*2;
        const uint32_t sWl = s0 + 3*TILE*2;

        #pragma unroll
        for (int ks = 0; ks < 4; ks++) {
            const int kk = ks * 16;
            uint32_t bh[8][2], bl[8][2];
            #pragma unroll
            for (int p = 0; p < 4; p++) {
                int nrow = wn*64 + p*16 + w_row;
                uint32_t off = (uint32_t)(nrow * SROW + kk + w_ch) * 2;
                uint32_t t[4];
                ldsm_x4(t, sWh + off);
                bh[2*p][0]=t[0]; bh[2*p][1]=t[1]; bh[2*p+1][0]=t[2]; bh[2*p+1][1]=t[3];
                ldsm_x4(t, sWl + off);
                bl[2*p][0]=t[0]; bl[2*p][1]=t[1]; bl[2*p+1][0]=t[2]; bl[2*p+1][1]=t[3];
            }
            uint32_t ah[2][4], al[2][4];
            #pragma unroll
            for (int mf = 0; mf < 2; mf++) {
                int row = wm*32 + mf*16 + a_row;
                uint32_t off = (uint32_t)(row * SROW + kk + a_ch) * 2;
                ldsm_x4(ah[mf], sAh + off);
                ldsm_x4(al[mf], sAl + off);
            }
            #pragma unroll
            for (int nf = 0; nf < 8; nf++) {
                #pragma unroll
                for (int mf = 0; mf < 2; mf++) {
                    hmma(acc[mf][nf], ah[mf], bh[nf]);
                    hmma(acc[mf][nf], ah[mf], bl[nf]);
                    hmma(acc[mf][nf], al[mf], bh[nf]);
                }
            }
        }
        __syncthreads();
    }

    #pragma unroll
    for (int mf = 0; mf < 2; mf++) {
        int row = m0 + wm*32 + mf*16 + g;
        #pragma unroll
        for (int nf = 0; nf < 8; nf++) {
            int col = n0 + wn*64 + nf*8 + q4*2;
            *(float2*)&out[(size_t)row * ldc + col]       = make_float2(acc[mf][nf][0], acc[mf][nf][1]);
            *(float2*)&out[(size_t)(row + 8) * ldc + col] = make_float2(acc[mf][nf][2], acc[mf][nf][3]);
        }
    }
}

// ---------------- scan pass 1: chunk end states only ----------------
__global__ __launch_bounds__(256) void k_scan1() {
    const int b = blockIdx.x / NCHUNK, c = blockIdx.x % NCHUNK;
    const int n = threadIdx.x;
    const float Ar = g_Ar[n], Ai = g_Ai[n];
    size_t base = ((size_t)b*SEQ + (size_t)c*CHUNK) * 512 + n;
    float hr = 0.f, hi = 0.f;
    #pragma unroll 8
    for (int j = 0; j < CHUNK; j++) {
        float ur = g_u[base], ui = g_u[base + 256];
        float nhr = fmaf(Ar, hr, fmaf(-Ai, hi, ur));
        float nhi = fmaf(Ar, hi, fmaf( Ai, hr, ui));
        hr = nhr; hi = nhi;
        base += 512;
    }
    g_cr[(b*NCHUNK + c)*NST + n] = hr;
    g_ci[(b*NCHUNK + c)*NST + n] = hi;
}

// ---------------- scan pass 2: cross-chunk prefix ----------------
__global__ __launch_bounds__(256) void k_scan2() {
    const int b = blockIdx.x;
    const int n = threadIdx.x;
    const float Ar = g_ALr[n], Ai = g_ALi[n];
    float hr = 0.f, hi = 0.f;
    for (int cb = 0; cb < 4; cb++) {
        float cr[16], ci[16];
        #pragma unroll
        for (int i = 0; i < 16; i++) {
            int idx = (b*NCHUNK + cb*16 + i)*NST + n;
            cr[i] = g_cr[idx]; ci[i] = g_ci[idx];
        }
        #pragma unroll
        for (int i = 0; i < 16; i++) {
            int idx = (b*NCHUNK + cb*16 + i)*NST + n;
            g_pr[idx] = hr; g_pi[idx] = hi;
            float nhr = fmaf(Ar, hr, fmaf(-Ai, hi, cr[i]));
            float nhi = fmaf(Ar, hi, fmaf( Ai, hr, ci[i]));
            hr = nhr; hi = nhi;
        }
    }
}

// ---------------- scan pass 3: full scan with carry, emit h as bf16 hi/lo ----------------
__global__ __launch_bounds__(256) void k_scan3() {
    const int b = blockIdx.x / NCHUNK, c = blockIdx.x % NCHUNK;
    const int n = threadIdx.x;
    const float Ar = g_Ar[n], Ai = g_Ai[n];
    float hr = g_pr[(b*NCHUNK + c)*NST + n];
    float hi = g_pi[(b*NCHUNK + c)*NST + n];
    size_t base = ((size_t)b*SEQ + (size_t)c*CHUNK) * 512 + n;
    #pragma unroll 8
    for (int j = 0; j < CHUNK; j++) {
        float ur = g_u[base], ui = g_u[base + 256];
        float nhr = fmaf(Ar, hr, fmaf(-Ai, hi, ur));
        float nhi = fmaf(Ar, hi, fmaf( Ai, hr, ui));
        hr = nhr; hi = nhi;
        bsplit(hr, g_hh[base],       g_hl[base]);
        bsplit(hi, g_hh[base + 256], g_hl[base + 256]);
        base += 512;
    }
}

// ---------------- launch ----------------
extern "C" void kernel_launch(void* const* d_in, const int* in_sizes, int n_in,
                              void* d_out, int out_size) {
    const float* x   = (const float*)d_in[0];
    const float* llr = (const float*)d_in[1];
    const float* lim = (const float*)d_in[2];
    const float* ldt = (const float*)d_in[3];
    const float* Bm  = (const float*)d_in[4];
    const float* Cr  = (const float*)d_in[5];
    const float* Ci  = (const float*)d_in[6];
    float* out = (float*)d_out;

    cudaFuncSetAttribute(k_gemm, cudaFuncAttributeMaxDynamicSharedMemorySize, SMEM_SZ);

    bf16 *xh, *xl, *w1h, *w1l, *w2h, *w2l, *hh, *hl;
    float *u;
    cudaGetSymbolAddress((void**)&xh, g_xh);
    cudaGetSymbolAddress((void**)&xl, g_xl);
    cudaGetSymbolAddress((void**)&w1h, g_W1h);
    cudaGetSymbolAddress((void**)&w1l, g_W1l);
    cudaGetSymbolAddress((void**)&w2h, g_W2h);
    cudaGetSymbolAddress((void**)&w2l, g_W2l);
    cudaGetSymbolAddress((void**)&hh, g_hh);
    cudaGetSymbolAddress((void**)&hl, g_hl);
    cudaGetSymbolAddress((void**)&u, g_u);

    k_setup<<<1, 256>>>(llr, lim, ldt);
    k_w1<<<(256*256)/256, 256>>>(Bm);
    k_w2<<<(256*512)/256, 256>>>(Cr, Ci);
    k_cvt<<<(M_TOT*DIN/4)/256, 256>>>(x);
    // GEMM1: u[M,512] = x @ [Bbar_r;Bbar_i]^T
    k_gemm<<<dim3(512/128, M_TOT/128), 256, SMEM_SZ>>>(xh, xl, DIN, w1h, w1l, u, 512, DIN);
    k_scan1<<<BT*NCHUNK, 256>>>();
    k_scan2<<<BT, 256>>>();
    k_scan3<<<BT*NCHUNK, 256>>>();
    // GEMM2: out[M,256] = [hr|hi] @ [Cr|-Ci]^T
    k_gemm<<<dim3(DOUT/128, M_TOT/128), 256, SMEM_SZ>>>(hh, hl, 512, w2h, w2l, out, DOUT, 512);
}

// round 8
// speedup vs baseline: 2.4812x; 1.1057x over previous
#include <cuda_runtime.h>
#include <cuda_bf16.h>
#include <cstdint>

#define BT 8
#define SEQ 4096
#define NST 256
#define DIN 256
#define DOUT 256
#define M_TOT (BT*SEQ)          // 32768
#define CHUNK 64
#define NCHUNK (SEQ/CHUNK)      // 64

typedef unsigned long long u64;
typedef __nv_bfloat16 bf16;

// ---------------- device scratch ----------------
__device__ float g_Ar[NST], g_Ai[NST];
__device__ float g_ALr[NST], g_ALi[NST];
__device__ float g_wr[NST], g_wi[NST];
__device__ bf16  g_xh[(size_t)M_TOT*DIN], g_xl[(size_t)M_TOT*DIN];
__device__ bf16  g_W1h[512*DIN], g_W1l[512*DIN];   // [Bbar_r; Bbar_i]
__device__ bf16  g_W2h[DOUT*512], g_W2l[DOUT*512]; // [Cr | -Ci]
__device__ float g_u[(size_t)M_TOT*512];      // u: [:,0:256]=real  [:,256:512]=imag
__device__ bf16  g_hh[(size_t)M_TOT*512];     // h hi: [hr | hi_part]
__device__ bf16  g_hl[(size_t)M_TOT*512];     // h lo
__device__ float g_cr[BT*NCHUNK*NST], g_ci[BT*NCHUNK*NST];
__device__ float g_pr[BT*NCHUNK*NST], g_pi[BT*NCHUNK*NST];

__device__ __forceinline__ void bsplit(float v, bf16& h, bf16& l) {
    h = __float2bfloat16(v);
    l = __float2bfloat16(v - __bfloat162float(h));
}

// mma.sync m16n8k16 row.col bf16 -> f32 accumulate
__device__ __forceinline__ void hmma(float* d, const uint32_t* a, const uint32_t* b) {
    asm volatile(
        "mma.sync.aligned.m16n8k16.row.col.f32.bf16.bf16.f32 "
        "{%0,%1,%2,%3}, {%4,%5,%6,%7}, {%8,%9}, {%0,%1,%2,%3};"
        : "+f"(d[0]), "+f"(d[1]), "+f"(d[2]), "+f"(d[3])
        : "r"(a[0]), "r"(a[1]), "r"(a[2]), "r"(a[3]), "r"(b[0]), "r"(b[1]));
}
__device__ __forceinline__ void ldsm_x4(uint32_t* r, uint32_t addr) {
    asm volatile("ldmatrix.sync.aligned.m8n8.x4.shared.b16 {%0,%1,%2,%3}, [%4];"
        : "=r"(r[0]), "=r"(r[1]), "=r"(r[2]), "=r"(r[3]) : "r"(addr));
}
__device__ __forceinline__ void cpa16(uint32_t saddr, const void* g) {
    asm volatile("cp.async.cg.shared.global [%0], [%1], 16;" :: "r"(saddr), "l"(g));
}
__device__ __forceinline__ uint32_t smem_u32(const void* p) {
    uint32_t a;
    asm("{ .reg .u64 t; cvta.to.shared.u64 t, %1; cvt.u32.u64 %0, t; }" : "=r"(a) : "l"(p));
    return a;
}
// swizzled byte offset inside a R x 64 bf16 tile: row-major 64-elem rows,
// 8-elem (16B) groups XOR'd by (row & 7) -> conflict-free ldmatrix & cp.async
__device__ __forceinline__ uint32_t swz(int row, int g8) {
    return (uint32_t)(row * 64 + ((g8 ^ (row & 7)) * 8)) * 2;
}

// ---------------- setup: per-n scalars only ----------------
__global__ void k_setup(const float* __restrict__ llr, const float* __restrict__ lim,
                        const float* __restrict__ ldt) {
    int n = threadIdx.x;
    float lr = -expf(llr[n]);
    float li = lim[n];
    float dt = expf(ldt[n]);
    dt = fminf(fmaxf(dt, 0.005f), 0.1f);
    float dr = 1.f - 0.5f * dt * lr;
    float di = -0.5f * dt * li;
    float nr = 1.f + 0.5f * dt * lr;
    float ni = 0.5f * dt * li;
    float inv = 1.f / (dr*dr + di*di);
    float Ar = (nr*dr + ni*di) * inv;
    float Ai = (ni*dr - nr*di) * inv;
    g_Ar[n] = Ar; g_Ai[n] = Ai;
    g_wr[n] = dt * dr * inv;
    g_wi[n] = -dt * di * inv;
    float pr = 1.f, pi = 0.f;
    for (int j = 0; j < CHUNK; j++) {
        float t = pr*Ar - pi*Ai;
        pi = pr*Ai + pi*Ar;
        pr = t;
    }
    g_ALr[n] = pr; g_ALi[n] = pi;
}

__global__ __launch_bounds__(256) void k_w1(const float* __restrict__ Bm) {
    int idx = blockIdx.x * blockDim.x + threadIdx.x;   // over 256*256
    int n = idx >> 8, k = idx & 255;
    float b = Bm[idx];
    bsplit(g_wr[n] * b, g_W1h[idx],             g_W1l[idx]);
    bsplit(g_wi[n] * b, g_W1h[(256+n)*DIN + k], g_W1l[(256+n)*DIN + k]);
}

__global__ void k_w2(const float* __restrict__ Cr, const float* __restrict__ Ci) {
    int idx = blockIdx.x * blockDim.x + threadIdx.x;   // over 256*512
    int d = idx >> 9, k = idx & 511;
    float v = (k < 256) ? Cr[d*256 + k] : -Ci[d*256 + (k - 256)];
    bsplit(v, g_W2h[idx], g_W2l[idx]);
}

__global__ __launch_bounds__(256) void k_cvt(const float* __restrict__ x) {
    size_t i = (size_t)(blockIdx.x * blockDim.x + threadIdx.x) * 4;
    float4 v = *(const float4*)&x[i];
    bf16 h0,l0,h1,l1,h2,l2,h3,l3;
    bsplit(v.x,h0,l0); bsplit(v.y,h1,l1); bsplit(v.z,h2,l2); bsplit(v.w,h3,l3);
    __nv_bfloat162 hh0={h0,h1}, hh1={h2,h3}, ll0={l0,l1}, ll1={l2,l3};
    *(uint2*)&g_xh[i] = make_uint2(*(uint32_t*)&hh0, *(uint32_t*)&hh1);
    *(uint2*)&g_xl[i] = make_uint2(*(uint32_t*)&ll0, *(uint32_t*)&ll1);
}

// ---------------- HMMA GEMM, M-tile = MF*64, N-tile 128, swizzled smem ----------------
// 8 warps: wm = wid>>1 covers MF*16 rows, wn = wid&1 covers 64 cols.
template<int MF>
__global__ __launch_bounds__(256, 1) void k_gemm(
    const bf16* __restrict__ Ah, const bf16* __restrict__ Al, int lda,
    const bf16* __restrict__ Wh, const bf16* __restrict__ Wl,
    float* __restrict__ out, int ldc, int Kdim)
{
    constexpr int MT = MF * 64;                 // M tile rows
    constexpr int A_EL = MT * 64;               // per A tile (elements)
    constexpr int W_EL = 128 * 64;
    constexpr int STAGE_EL = 2 * A_EL + 2 * W_EL;

    extern __shared__ bf16 smem[];
    const uint32_t sb = smem_u32(smem);
    const int tid = threadIdx.x;
    const int wid = tid >> 5, lane = tid & 31;
    const int m0 = blockIdx.y * MT;
    const int n0 = blockIdx.x * 128;
    const int wm = wid >> 1;
    const int wn = wid & 1;
    const int g  = lane >> 2;
    const int q4 = lane & 3;

    float acc[MF][8][4];
    #pragma unroll
    for (int i = 0; i < MF; i++)
        #pragma unroll
        for (int j = 0; j < 8; j++)
            #pragma unroll
            for (int r = 0; r < 4; r++) acc[i][j][r] = 0.f;

    const int nchunks = Kdim / 64;

    const int a_row = (lane & 7) + ((lane >> 3) & 1) * 8;
    const int a_g8  = lane >> 4;                // 0/1
    const int w_row = (lane & 7) + ((lane >> 4) & 1) * 8;
    const int w_g8  = (lane >> 3) & 1;

    auto prefetch = [&](int stage, int ch) {
        const int k0 = ch * 64;
        const uint32_t s0 = sb + (uint32_t)stage * STAGE_EL * 2;
        const uint32_t sAh = s0, sAl = s0 + A_EL*2;
        const uint32_t sWh = s0 + 2*A_EL*2, sWl = s0 + 2*A_EL*2 + W_EL*2;
        #pragma unroll
        for (int i = 0; i < MF*2; i++) {        // A: MT*8 16B-vectors, hi+lo
            int v = tid + i * 256;
            int row = v >> 3, q = v & 7;
            uint32_t so = swz(row, q);
            const size_t ga = (size_t)(m0 + row) * lda + k0 + q * 8;
            cpa16(sAh + so, Ah + ga);
            cpa16(sAl + so, Al + ga);
        }
        #pragma unroll
        for (int i = 0; i < 4; i++) {           // W: 1024 vectors, hi+lo
            int v = tid + i * 256;
            int row = v >> 3, q = v & 7;
            uint32_t so = swz(row, q);
            const size_t gw = (size_t)(n0 + row) * Kdim + k0 + q * 8;
            cpa16(sWh + so, Wh + gw);
            cpa16(sWl + so, Wl + gw);
        }
        asm volatile("cp.async.commit_group;");
    };

    prefetch(0, 0);

    for (int ch = 0; ch < nchunks; ch++) {
        const int st = ch & 1;
        if (ch + 1 < nchunks) {
            prefetch(st ^ 1, ch + 1);
            asm volatile("cp.async.wait_group 1;");
        } else {
            asm volatile("cp.async.wait_group 0;");
        }
        __syncthreads();

        const uint32_t s0 = sb + (uint32_t)st * STAGE_EL * 2;
        const uint32_t sAh = s0, sAl = s0 + A_EL*2;
        const uint32_t sWh = s0 + 2*A_EL*2, sWl = s0 + 2*A_EL*2 + W_EL*2;

        #pragma unroll
        for (int ks = 0; ks < 4; ks++) {
            uint32_t bh[8][2], bl[8][2];
            #pragma unroll
            for (int p = 0; p < 4; p++) {
                int nrow = wn*64 + p*16 + w_row;
                uint32_t off = swz(nrow, ks*2 + w_g8);
                uint32_t t[4];
                ldsm_x4(t, sWh + off);
                bh[2*p][0]=t[0]; bh[2*p][1]=t[1]; bh[2*p+1][0]=t[2]; bh[2*p+1][1]=t[3];
                ldsm_x4(t, sWl + off);
                bl[2*p][0]=t[0]; bl[2*p][1]=t[1]; bl[2*p+1][0]=t[2]; bl[2*p+1][1]=t[3];
            }
            uint32_t ah[MF][4], al[MF][4];
            #pragma unroll
            for (int mf = 0; mf < MF; mf++) {
                int row = wm*(MF*16) + mf*16 + a_row;
                uint32_t off = swz(row, ks*2 + a_g8);
                ldsm_x4(ah[mf], sAh + off);
                ldsm_x4(al[mf], sAl + off);
            }
            #pragma unroll
            for (int nf = 0; nf < 8; nf++) {
                #pragma unroll
                for (int mf = 0; mf < MF; mf++) {
                    hmma(acc[mf][nf], ah[mf], bh[nf]);
                    hmma(acc[mf][nf], ah[mf], bl[nf]);
                    hmma(acc[mf][nf], al[mf], bh[nf]);
                }
            }
        }
        __syncthreads();
    }

    #pragma unroll
    for (int mf = 0; mf < MF; mf++) {
        int row = m0 + wm*(MF*16) + mf*16 + g;
        #pragma unroll
        for (int nf = 0; nf < 8; nf++) {
            int col = n0 + wn*64 + nf*8 + q4*2;
            *(float2*)&out[(size_t)row * ldc + col]       = make_float2(acc[mf][nf][0], acc[mf][nf][1]);
            *(float2*)&out[(size_t)(row + 8) * ldc + col] = make_float2(acc[mf][nf][2], acc[mf][nf][3]);
        }
    }
}

#define GEMM_MF 4
#define GEMM_SMEM ((2*(2*(GEMM_MF*64*64) + 2*(128*64)))*2)

// ---------------- scan pass 1: chunk end states only ----------------
__global__ __launch_bounds__(256) void k_scan1() {
    const int b = blockIdx.x / NCHUNK, c = blockIdx.x % NCHUNK;
    const int n = threadIdx.x;
    const float Ar = g_Ar[n], Ai = g_Ai[n];
    size_t base = ((size_t)b*SEQ + (size_t)c*CHUNK) * 512 + n;
    float hr = 0.f, hi = 0.f;
    #pragma unroll 8
    for (int j = 0; j < CHUNK; j++) {
        float ur = g_u[base], ui = g_u[base + 256];
        float nhr = fmaf(Ar, hr, fmaf(-Ai, hi, ur));
        float nhi = fmaf(Ar, hi, fmaf( Ai, hr, ui));
        hr = nhr; hi = nhi;
        base += 512;
    }
    g_cr[(b*NCHUNK + c)*NST + n] = hr;
    g_ci[(b*NCHUNK + c)*NST + n] = hi;
}

// ---------------- scan pass 2: cross-chunk prefix ----------------
__global__ __launch_bounds__(256) void k_scan2() {
    const int b = blockIdx.x;
    const int n = threadIdx.x;
    const float Ar = g_ALr[n], Ai = g_ALi[n];
    float hr = 0.f, hi = 0.f;
    for (int cb = 0; cb < 4; cb++) {
        float cr[16], ci[16];
        #pragma unroll
        for (int i = 0; i < 16; i++) {
            int idx = (b*NCHUNK + cb*16 + i)*NST + n;
            cr[i] = g_cr[idx]; ci[i] = g_ci[idx];
        }
        #pragma unroll
        for (int i = 0; i < 16; i++) {
            int idx = (b*NCHUNK + cb*16 + i)*NST + n;
            g_pr[idx] = hr; g_pi[idx] = hi;
            float nhr = fmaf(Ar, hr, fmaf(-Ai, hi, cr[i]));
            float nhi = fmaf(Ar, hi, fmaf( Ai, hr, ci[i]));
            hr = nhr; hi = nhi;
        }
    }
}

// ---------------- scan pass 3: full scan with carry, emit h as bf16 hi/lo ----------------
__global__ __launch_bounds__(256) void k_scan3() {
    const int b = blockIdx.x / NCHUNK, c = blockIdx.x % NCHUNK;
    const int n = threadIdx.x;
    const float Ar = g_Ar[n], Ai = g_Ai[n];
    float hr = g_pr[(b*NCHUNK + c)*NST + n];
    float hi = g_pi[(b*NCHUNK + c)*NST + n];
    size_t base = ((size_t)b*SEQ + (size_t)c*CHUNK) * 512 + n;
    #pragma unroll 8
    for (int j = 0; j < CHUNK; j++) {
        float ur = g_u[base], ui = g_u[base + 256];
        float nhr = fmaf(Ar, hr, fmaf(-Ai, hi, ur));
        float nhi = fmaf(Ar, hi, fmaf( Ai, hr, ui));
        hr = nhr; hi = nhi;
        bsplit(hr, g_hh[base],       g_hl[base]);
        bsplit(hi, g_hh[base + 256], g_hl[base + 256]);
        base += 512;
    }
}

// ---------------- launch ----------------
extern "C" void kernel_launch(void* const* d_in, const int* in_sizes, int n_in,
                              void* d_out, int out_size) {
    const float* x   = (const float*)d_in[0];
    const float* llr = (const float*)d_in[1];
    const float* lim = (const float*)d_in[2];
    const float* ldt = (const float*)d_in[3];
    const float* Bm  = (const float*)d_in[4];
    const float* Cr  = (const float*)d_in[5];
    const float* Ci  = (const float*)d_in[6];
    float* out = (float*)d_out;

    cudaFuncSetAttribute(k_gemm<GEMM_MF>, cudaFuncAttributeMaxDynamicSharedMemorySize, GEMM_SMEM);

    bf16 *xh, *xl, *w1h, *w1l, *w2h, *w2l, *hh, *hl;
    float *u;
    cudaGetSymbolAddress((void**)&xh, g_xh);
    cudaGetSymbolAddress((void**)&xl, g_xl);
    cudaGetSymbolAddress((void**)&w1h, g_W1h);
    cudaGetSymbolAddress((void**)&w1l, g_W1l);
    cudaGetSymbolAddress((void**)&w2h, g_W2h);
    cudaGetSymbolAddress((void**)&w2l, g_W2l);
    cudaGetSymbolAddress((void**)&hh, g_hh);
    cudaGetSymbolAddress((void**)&hl, g_hl);
    cudaGetSymbolAddress((void**)&u, g_u);

    k_setup<<<1, 256>>>(llr, lim, ldt);
    k_w1<<<(256*256)/256, 256>>>(Bm);
    k_w2<<<(256*512)/256, 256>>>(Cr, Ci);
    k_cvt<<<(M_TOT*DIN/4)/256, 256>>>(x);
    // GEMM1: u[M,512] = x @ [Bbar_r;Bbar_i]^T
    k_gemm<GEMM_MF><<<dim3(512/128, M_TOT/(GEMM_MF*64)), 256, GEMM_SMEM>>>(xh, xl, DIN, w1h, w1l, u, 512, DIN);
    k_scan1<<<BT*NCHUNK, 256>>>();
    k_scan2<<<BT, 256>>>();
    k_scan3<<<BT*NCHUNK, 256>>>();
    // GEMM2: out[M,256] = [hr|hi] @ [Cr|-Ci]^T
    k_gemm<GEMM_MF><<<dim3(DOUT/128, M_TOT/(GEMM_MF*64)), 256, GEMM_SMEM>>>(hh, hl, 512, w2h, w2l, out, DOUT, 512);
}

// round 9
// speedup vs baseline: 2.5050x; 1.0096x over previous
#include <cuda_runtime.h>
#include <cuda_bf16.h>
#include <cstdint>

#define BT 8
#define SEQ 4096
#define NST 256
#define DIN 256
#define DOUT 256
#define M_TOT (BT*SEQ)          // 32768
#define CHUNK 64
#define NCHUNK (SEQ/CHUNK)      // 64

typedef unsigned long long u64;
typedef __nv_bfloat16 bf16;

// ---------------- device scratch ----------------
__device__ float g_Ar[NST], g_Ai[NST];
__device__ float g_ALr[NST], g_ALi[NST];
__device__ float g_wr[NST], g_wi[NST];
__device__ bf16  g_xh[(size_t)M_TOT*DIN], g_xl[(size_t)M_TOT*DIN];
__device__ bf16  g_W1h[512*DIN], g_W1l[512*DIN];   // [Bbar_r; Bbar_i]
__device__ bf16  g_W2h[DOUT*512], g_W2l[DOUT*512]; // [Cr | -Ci]
__device__ float g_u[(size_t)M_TOT*512];      // u: [:,0:256]=real  [:,256:512]=imag
__device__ bf16  g_hh[(size_t)M_TOT*512];     // h hi: [hr | hi_part]
__device__ bf16  g_hl[(size_t)M_TOT*512];     // h lo
__device__ float g_cr[BT*NCHUNK*NST], g_ci[BT*NCHUNK*NST];
__device__ float g_pr[BT*NCHUNK*NST], g_pi[BT*NCHUNK*NST];

__device__ __forceinline__ void bsplit(float v, bf16& h, bf16& l) {
    h = __float2bfloat16(v);
    l = __float2bfloat16(v - __bfloat162float(h));
}

// mma.sync m16n8k16 row.col bf16 -> f32 accumulate
__device__ __forceinline__ void hmma(float* d, const uint32_t* a, const uint32_t* b) {
    asm volatile(
        "mma.sync.aligned.m16n8k16.row.col.f32.bf16.bf16.f32 "
        "{%0,%1,%2,%3}, {%4,%5,%6,%7}, {%8,%9}, {%0,%1,%2,%3};"
        : "+f"(d[0]), "+f"(d[1]), "+f"(d[2]), "+f"(d[3])
        : "r"(a[0]), "r"(a[1]), "r"(a[2]), "r"(a[3]), "r"(b[0]), "r"(b[1]));
}
__device__ __forceinline__ void ldsm_x4(uint32_t* r, uint32_t addr) {
    asm volatile("ldmatrix.sync.aligned.m8n8.x4.shared.b16 {%0,%1,%2,%3}, [%4];"
        : "=r"(r[0]), "=r"(r[1]), "=r"(r[2]), "=r"(r[3]) : "r"(addr));
}
__device__ __forceinline__ void cpa16(uint32_t saddr, const void* g) {
    asm volatile("cp.async.cg.shared.global [%0], [%1], 16;" :: "r"(saddr), "l"(g));
}
__device__ __forceinline__ uint32_t smem_u32(const void* p) {
    uint32_t a;
    asm("{ .reg .u64 t; cvta.to.shared.u64 t, %1; cvt.u32.u64 %0, t; }" : "=r"(a) : "l"(p));
    return a;
}
// swizzled byte offset inside a R x 64 bf16 tile
__device__ __forceinline__ uint32_t swz(int row, int g8) {
    return (uint32_t)(row * 64 + ((g8 ^ (row & 7)) * 8)) * 2;
}

// ---------------- setup: per-n scalars only ----------------
__global__ void k_setup(const float* __restrict__ llr, const float* __restrict__ lim,
                        const float* __restrict__ ldt) {
    int n = threadIdx.x;
    float lr = -expf(llr[n]);
    float li = lim[n];
    float dt = expf(ldt[n]);
    dt = fminf(fmaxf(dt, 0.005f), 0.1f);
    float dr = 1.f - 0.5f * dt * lr;
    float di = -0.5f * dt * li;
    float nr = 1.f + 0.5f * dt * lr;
    float ni = 0.5f * dt * li;
    float inv = 1.f / (dr*dr + di*di);
    float Ar = (nr*dr + ni*di) * inv;
    float Ai = (ni*dr - nr*di) * inv;
    g_Ar[n] = Ar; g_Ai[n] = Ai;
    g_wr[n] = dt * dr * inv;
    g_wi[n] = -dt * di * inv;
    float pr = 1.f, pi = 0.f;
    for (int j = 0; j < CHUNK; j++) {
        float t = pr*Ar - pi*Ai;
        pi = pr*Ai + pi*Ar;
        pr = t;
    }
    g_ALr[n] = pr; g_ALi[n] = pi;
}

__global__ __launch_bounds__(256) void k_w1(const float* __restrict__ Bm) {
    int idx = blockIdx.x * blockDim.x + threadIdx.x;   // over 256*256
    int n = idx >> 8, k = idx & 255;
    float b = Bm[idx];
    bsplit(g_wr[n] * b, g_W1h[idx],             g_W1l[idx]);
    bsplit(g_wi[n] * b, g_W1h[(256+n)*DIN + k], g_W1l[(256+n)*DIN + k]);
}

__global__ void k_w2(const float* __restrict__ Cr, const float* __restrict__ Ci) {
    int idx = blockIdx.x * blockDim.x + threadIdx.x;   // over 256*512
    int d = idx >> 9, k = idx & 511;
    float v = (k < 256) ? Cr[d*256 + k] : -Ci[d*256 + (k - 256)];
    bsplit(v, g_W2h[idx], g_W2l[idx]);
}

__global__ __launch_bounds__(256) void k_cvt(const float* __restrict__ x) {
    size_t i = (size_t)(blockIdx.x * blockDim.x + threadIdx.x) * 4;
    float4 v = *(const float4*)&x[i];
    bf16 h0,l0,h1,l1,h2,l2,h3,l3;
    bsplit(v.x,h0,l0); bsplit(v.y,h1,l1); bsplit(v.z,h2,l2); bsplit(v.w,h3,l3);
    __nv_bfloat162 hh0={h0,h1}, hh1={h2,h3}, ll0={l0,l1}, ll1={l2,l3};
    *(uint2*)&g_xh[i] = make_uint2(*(uint32_t*)&hh0, *(uint32_t*)&hh1);
    *(uint2*)&g_xl[i] = make_uint2(*(uint32_t*)&ll0, *(uint32_t*)&ll1);
}

// ---------------- HMMA GEMM, M-tile = MF*64, N-tile 128, swizzled smem ----------------
// single __syncthreads per chunk; prefetch(ch+1) issued before compute(ch)
template<int MF>
__global__ __launch_bounds__(256, 1) void k_gemm(
    const bf16* __restrict__ Ah, const bf16* __restrict__ Al, int lda,
    const bf16* __restrict__ Wh, const bf16* __restrict__ Wl,
    float* __restrict__ out, int ldc, int Kdim)
{
    constexpr int MT = MF * 64;
    constexpr int A_EL = MT * 64;
    constexpr int W_EL = 128 * 64;
    constexpr int STAGE_EL = 2 * A_EL + 2 * W_EL;

    extern __shared__ bf16 smem[];
    const uint32_t sb = smem_u32(smem);
    const int tid = threadIdx.x;
    const int wid = tid >> 5, lane = tid & 31;
    const int m0 = blockIdx.y * MT;
    const int n0 = blockIdx.x * 128;
    const int wm = wid >> 1;
    const int wn = wid & 1;
    const int g  = lane >> 2;
    const int q4 = lane & 3;

    float acc[MF][8][4];
    #pragma unroll
    for (int i = 0; i < MF; i++)
        #pragma unroll
        for (int j = 0; j < 8; j++)
            #pragma unroll
            for (int r = 0; r < 4; r++) acc[i][j][r] = 0.f;

    const int nchunks = Kdim / 64;

    const int a_row = (lane & 7) + ((lane >> 3) & 1) * 8;
    const int a_g8  = lane >> 4;
    const int w_row = (lane & 7) + ((lane >> 4) & 1) * 8;
    const int w_g8  = (lane >> 3) & 1;

    auto prefetch = [&](int stage, int ch) {
        const int k0 = ch * 64;
        const uint32_t s0 = sb + (uint32_t)stage * STAGE_EL * 2;
        const uint32_t sAh = s0, sAl = s0 + A_EL*2;
        const uint32_t sWh = s0 + 2*A_EL*2, sWl = s0 + 2*A_EL*2 + W_EL*2;
        #pragma unroll
        for (int i = 0; i < MF*2; i++) {
            int v = tid + i * 256;
            int row = v >> 3, q = v & 7;
            uint32_t so = swz(row, q);
            const size_t ga = (size_t)(m0 + row) * lda + k0 + q * 8;
            cpa16(sAh + so, Ah + ga);
            cpa16(sAl + so, Al + ga);
        }
        #pragma unroll
        for (int i = 0; i < 4; i++) {
            int v = tid + i * 256;
            int row = v >> 3, q = v & 7;
            uint32_t so = swz(row, q);
            const size_t gw = (size_t)(n0 + row) * Kdim + k0 + q * 8;
            cpa16(sWh + so, Wh + gw);
            cpa16(sWl + so, Wl + gw);
        }
        asm volatile("cp.async.commit_group;");
    };

    prefetch(0, 0);

    for (int ch = 0; ch < nchunks; ch++) {
        const int st = ch & 1;
        asm volatile("cp.async.wait_group 0;");
        __syncthreads();                 // data for ch visible; chunk ch-1 fully consumed
        if (ch + 1 < nchunks) prefetch(st ^ 1, ch + 1);   // overlaps compute below

        const uint32_t s0 = sb + (uint32_t)st * STAGE_EL * 2;
        const uint32_t sAh = s0, sAl = s0 + A_EL*2;
        const uint32_t sWh = s0 + 2*A_EL*2, sWl = s0 + 2*A_EL*2 + W_EL*2;

        #pragma unroll
        for (int ks = 0; ks < 4; ks++) {
            uint32_t bh[8][2], bl[8][2];
            #pragma unroll
            for (int p = 0; p < 4; p++) {
                int nrow = wn*64 + p*16 + w_row;
                uint32_t off = swz(nrow, ks*2 + w_g8);
                uint32_t t[4];
                ldsm_x4(t, sWh + off);
                bh[2*p][0]=t[0]; bh[2*p][1]=t[1]; bh[2*p+1][0]=t[2]; bh[2*p+1][1]=t[3];
                ldsm_x4(t, sWl + off);
                bl[2*p][0]=t[0]; bl[2*p][1]=t[1]; bl[2*p+1][0]=t[2]; bl[2*p+1][1]=t[3];
            }
            uint32_t ah[MF][4], al[MF][4];
            #pragma unroll
            for (int mf = 0; mf < MF; mf++) {
                int row = wm*(MF*16) + mf*16 + a_row;
                uint32_t off = swz(row, ks*2 + a_g8);
                ldsm_x4(ah[mf], sAh + off);
                ldsm_x4(al[mf], sAl + off);
            }
            #pragma unroll
            for (int nf = 0; nf < 8; nf++) {
                #pragma unroll
                for (int mf = 0; mf < MF; mf++) {
                    hmma(acc[mf][nf], ah[mf], bh[nf]);
                    hmma(acc[mf][nf], ah[mf], bl[nf]);
                    hmma(acc[mf][nf], al[mf], bh[nf]);
                }
            }
        }
    }

    #pragma unroll
    for (int mf = 0; mf < MF; mf++) {
        int row = m0 + wm*(MF*16) + mf*16 + g;
        #pragma unroll
        for (int nf = 0; nf < 8; nf++) {
            int col = n0 + wn*64 + nf*8 + q4*2;
            *(float2*)&out[(size_t)row * ldc + col]       = make_float2(acc[mf][nf][0], acc[mf][nf][1]);
            *(float2*)&out[(size_t)(row + 8) * ldc + col] = make_float2(acc[mf][nf][2], acc[mf][nf][3]);
        }
    }
}

#define GEMM_MF 4
#define GEMM_SMEM ((2*(2*(GEMM_MF*64*64) + 2*(128*64)))*2)

// ---------------- scan pass 1: chunk end states only ----------------
__global__ __launch_bounds__(256) void k_scan1() {
    const int b = blockIdx.x / NCHUNK, c = blockIdx.x % NCHUNK;
    const int n = threadIdx.x;
    const float Ar = g_Ar[n], Ai = g_Ai[n];
    size_t base = ((size_t)b*SEQ + (size_t)c*CHUNK) * 512 + n;
    float hr = 0.f, hi = 0.f;
    #pragma unroll 8
    for (int j = 0; j < CHUNK; j++) {
        float ur = g_u[base], ui = g_u[base + 256];
        float nhr = fmaf(Ar, hr, fmaf(-Ai, hi, ur));
        float nhi = fmaf(Ar, hi, fmaf( Ai, hr, ui));
        hr = nhr; hi = nhi;
        base += 512;
    }
    g_cr[(b*NCHUNK + c)*NST + n] = hr;
    g_ci[(b*NCHUNK + c)*NST + n] = hi;
}

// ---------------- scan pass 2: cross-chunk prefix ----------------
__global__ __launch_bounds__(256) void k_scan2() {
    const int b = blockIdx.x;
    const int n = threadIdx.x;
    const float Ar = g_ALr[n], Ai = g_ALi[n];
    float hr = 0.f, hi = 0.f;
    for (int cb = 0; cb < 4; cb++) {
        float cr[16], ci[16];
        #pragma unroll
        for (int i = 0; i < 16; i++) {
            int idx = (b*NCHUNK + cb*16 + i)*NST + n;
            cr[i] = g_cr[idx]; ci[i] = g_ci[idx];
        }
        #pragma unroll
        for (int i = 0; i < 16; i++) {
            int idx = (b*NCHUNK + cb*16 + i)*NST + n;
            g_pr[idx] = hr; g_pi[idx] = hi;
            float nhr = fmaf(Ar, hr, fmaf(-Ai, hi, cr[i]));
            float nhi = fmaf(Ar, hi, fmaf( Ai, hr, ci[i]));
            hr = nhr; hi = nhi;
        }
    }
}

// ---------------- scan pass 3: full scan with carry, emit h as bf16 hi/lo ----------------
__global__ __launch_bounds__(256) void k_scan3() {
    const int b = blockIdx.x / NCHUNK, c = blockIdx.x % NCHUNK;
    const int n = threadIdx.x;
    const float Ar = g_Ar[n], Ai = g_Ai[n];
    float hr = g_pr[(b*NCHUNK + c)*NST + n];
    float hi = g_pi[(b*NCHUNK + c)*NST + n];
    size_t base = ((size_t)b*SEQ + (size_t)c*CHUNK) * 512 + n;
    #pragma unroll 8
    for (int j = 0; j < CHUNK; j++) {
        float ur = g_u[base], ui = g_u[base + 256];
        float nhr = fmaf(Ar, hr, fmaf(-Ai, hi, ur));
        float nhi = fmaf(Ar, hi, fmaf( Ai, hr, ui));
        hr = nhr; hi = nhi;
        bsplit(hr, g_hh[base],       g_hl[base]);
        bsplit(hi, g_hh[base + 256], g_hl[base + 256]);
        base += 512;
    }
}

// ---------------- launch ----------------
extern "C" void kernel_launch(void* const* d_in, const int* in_sizes, int n_in,
                              void* d_out, int out_size) {
    const float* x   = (const float*)d_in[0];
    const float* llr = (const float*)d_in[1];
    const float* lim = (const float*)d_in[2];
    const float* ldt = (const float*)d_in[3];
    const float* Bm  = (const float*)d_in[4];
    const float* Cr  = (const float*)d_in[5];
    const float* Ci  = (const float*)d_in[6];
    float* out = (float*)d_out;

    cudaFuncSetAttribute(k_gemm<GEMM_MF>, cudaFuncAttributeMaxDynamicSharedMemorySize, GEMM_SMEM);

    bf16 *xh, *xl, *w1h, *w1l, *w2h, *w2l, *hh, *hl;
    float *u;
    cudaGetSymbolAddress((void**)&xh, g_xh);
    cudaGetSymbolAddress((void**)&xl, g_xl);
    cudaGetSymbolAddress((void**)&w1h, g_W1h);
    cudaGetSymbolAddress((void**)&w1l, g_W1l);
    cudaGetSymbolAddress((void**)&w2h, g_W2h);
    cudaGetSymbolAddress((void**)&w2l, g_W2l);
    cudaGetSymbolAddress((void**)&hh, g_hh);
    cudaGetSymbolAddress((void**)&hl, g_hl);
    cudaGetSymbolAddress((void**)&u, g_u);

    k_setup<<<1, 256>>>(llr, lim, ldt);
    k_w1<<<(256*256)/256, 256>>>(Bm);
    k_w2<<<(256*512)/256, 256>>>(Cr, Ci);
    k_cvt<<<(M_TOT*DIN/4)/256, 256>>>(x);
    // GEMM1: u[M,512] = x @ [Bbar_r;Bbar_i]^T
    k_gemm<GEMM_MF><<<dim3(512/128, M_TOT/(GEMM_MF*64)), 256, GEMM_SMEM>>>(xh, xl, DIN, w1h, w1l, u, 512, DIN);
    k_scan1<<<BT*NCHUNK, 256>>>();
    k_scan2<<<BT, 256>>>();
    k_scan3<<<BT*NCHUNK, 256>>>();
    // GEMM2: out[M,256] = [hr|hi] @ [Cr|-Ci]^T
    k_gemm<GEMM_MF><<<dim3(DOUT/128, M_TOT/(GEMM_MF*64)), 256, GEMM_SMEM>>>(hh, hl, 512, w2h, w2l, out, DOUT, 512);
}